// round 9
// baseline (speedup 1.0000x reference)
#include <cuda_runtime.h>
#include <math.h>

#define Bb 2
#define Ss 2048
#define Dd 1024
#define Hh 16
#define HD 64
#define Mm (Bb*Ss)      /* 4096 */
#define N3 (3*Dd)       /* 3072 */

// Scratch: q,k,v,attn_out in [B,H,S,hd] layout.
__device__ float g_q [Bb*Hh*Ss*HD];
__device__ float g_k [Bb*Hh*Ss*HD];
__device__ float g_v [Bb*Hh*Ss*HD];
__device__ float g_ao[Bb*Hh*Ss*HD];

__device__ __forceinline__ unsigned f2tf(float x) {
    unsigned y;
    asm("cvt.rna.tf32.f32 %0, %1;" : "=r"(y) : "f"(x));
    return y;
}

__device__ __forceinline__ void mma_tf32(float c[4],
                                         unsigned a0, unsigned a1, unsigned a2, unsigned a3,
                                         unsigned b0, unsigned b1) {
    asm volatile(
        "mma.sync.aligned.m16n8k8.row.col.f32.tf32.tf32.f32 "
        "{%0,%1,%2,%3},{%4,%5,%6,%7},{%8,%9},{%0,%1,%2,%3};\n"
        : "+f"(c[0]), "+f"(c[1]), "+f"(c[2]), "+f"(c[3])
        : "r"(a0), "r"(a1), "r"(a2), "r"(a3), "r"(b0), "r"(b1));
}

// ===========================================================================
// GEMM core v3: BM=256, BN=128, BK=8, 256 threads, 8 warps (4x2),
// warp tile 64x64 (4 m-frags x 8 n-frags) -> 1.0 LDS per mma.
// Double-buffered smem (33KB), register-prefetched LDG.
// ===========================================================================

__global__ void __launch_bounds__(256, 1) qkv_gemm(const float* __restrict__ X,
                                                   const float* __restrict__ W,
                                                   const float* __restrict__ bias)
{
    __shared__ unsigned As[2][256][12];   // [m][k] pad 12: frag reads conflict-free
    __shared__ unsigned Bs[2][8][132];    // [k][n] pad 132: frag reads conflict-free

    const int tid  = threadIdx.x;
    const int warp = tid >> 5, lane = tid & 31;
    const int wm = warp & 3, wn = warp >> 2;
    const int gid = lane >> 2, tig = lane & 3;
    const int bm = blockIdx.y * 256, bn = blockIdx.x * 128;

    // A loader: 512 float4 (256 rows x 8 cols), 2 per thread
    const int ar0 = tid >> 1,            ac0 = (tid & 1) * 4;
    const int ar1 = (tid + 256) >> 1,    ac1 = ((tid + 256) & 1) * 4;
    // B loader: 256 float4 (8 rows x 128 cols), 1 per thread
    const int brow = tid >> 5, bcn = (tid & 31) * 4;

    float acc[4][8][4] = {};
    float4 ra0, ra1, rb0;

    ra0 = *(const float4*)(X + (size_t)(bm + ar0) * Dd + ac0);
    ra1 = *(const float4*)(X + (size_t)(bm + ar1) * Dd + ac1);
    rb0 = *(const float4*)(W + (size_t)brow * N3 + bn + bcn);
    {
        uint4 u0 = { f2tf(ra0.x), f2tf(ra0.y), f2tf(ra0.z), f2tf(ra0.w) };
        uint4 u1 = { f2tf(ra1.x), f2tf(ra1.y), f2tf(ra1.z), f2tf(ra1.w) };
        *(uint4*)&As[0][ar0][ac0] = u0;
        *(uint4*)&As[0][ar1][ac1] = u1;
        uint4 v0 = { f2tf(rb0.x), f2tf(rb0.y), f2tf(rb0.z), f2tf(rb0.w) };
        *(uint4*)&Bs[0][brow][bcn] = v0;
    }
    __syncthreads();

    int cur = 0;
    for (int k0 = 0; k0 < Dd; k0 += 8) {
        const int kn = k0 + 8;
        if (kn < Dd) {
            ra0 = *(const float4*)(X + (size_t)(bm + ar0) * Dd + kn + ac0);
            ra1 = *(const float4*)(X + (size_t)(bm + ar1) * Dd + kn + ac1);
            rb0 = *(const float4*)(W + (size_t)(kn + brow) * N3 + bn + bcn);
        }

        unsigned af[4][4];
#pragma unroll
        for (int mf = 0; mf < 4; mf++) {
            const int rb = wm * 64 + mf * 16 + gid;
            af[mf][0] = As[cur][rb    ][tig];
            af[mf][1] = As[cur][rb + 8][tig];
            af[mf][2] = As[cur][rb    ][tig + 4];
            af[mf][3] = As[cur][rb + 8][tig + 4];
        }
#pragma unroll
        for (int nf = 0; nf < 8; nf++) {
            const int cb = wn * 64 + nf * 8 + gid;
            unsigned b0 = Bs[cur][tig    ][cb];
            unsigned b1 = Bs[cur][tig + 4][cb];
#pragma unroll
            for (int mf = 0; mf < 4; mf++)
                mma_tf32(acc[mf][nf], af[mf][0], af[mf][1], af[mf][2], af[mf][3], b0, b1);
        }

        if (kn < Dd) {
            const int nxt = cur ^ 1;
            uint4 u0 = { f2tf(ra0.x), f2tf(ra0.y), f2tf(ra0.z), f2tf(ra0.w) };
            uint4 u1 = { f2tf(ra1.x), f2tf(ra1.y), f2tf(ra1.z), f2tf(ra1.w) };
            *(uint4*)&As[nxt][ar0][ac0] = u0;
            *(uint4*)&As[nxt][ar1][ac1] = u1;
            uint4 v0 = { f2tf(rb0.x), f2tf(rb0.y), f2tf(rb0.z), f2tf(rb0.w) };
            *(uint4*)&Bs[nxt][brow][bcn] = v0;
            __syncthreads();
            cur = nxt;
        }
    }

    // Epilogue: bias + scatter into q/k/v head layout.
    const int which = bn / Dd;              // 0=q 1=k 2=v (BN=128 within one third)
    const int hbase = (bn % Dd) / HD;
    float* dst = (which == 0) ? g_q : ((which == 1) ? g_k : g_v);
#pragma unroll
    for (int mf = 0; mf < 4; mf++) {
#pragma unroll
        for (int nf = 0; nf < 8; nf++) {
            const int ncol = wn * 64 + nf * 8 + 2 * tig;
            const int h = hbase + (ncol >> 6);
            const int dd = ncol & 63;
            const float bi0 = bias[bn + ncol], bi1 = bias[bn + ncol + 1];
#pragma unroll
            for (int rr = 0; rr < 2; rr++) {
                const int m = bm + wm * 64 + mf * 16 + gid + rr * 8;
                const int b = m / Ss, s = m % Ss;
                float* drow = dst + ((size_t)(b * Hh + h) * Ss + s) * HD;
                drow[dd]     = acc[mf][nf][rr * 2]     + bi0;
                drow[dd + 1] = acc[mf][nf][rr * 2 + 1] + bi1;
            }
        }
    }
}

// ---------------------------------------------------------------------------
// Kernel 2: causal flash attention, tf32 mma (unchanged from R8).
// ---------------------------------------------------------------------------
#define SM_KS 0
#define SM_VS (32*68*4)                    /* 8704  */
#define SM_PS (SM_VS + 32*72*4)            /* 17920 */
#define SM_TOT (SM_PS + 128*36*4)          /* 36352 */

__global__ void __launch_bounds__(128, 2) attn_mma()
{
    __shared__ __align__(16) unsigned char smraw[SM_TOT];
    typedef unsigned (*arr68)[68];
    typedef unsigned (*arr72)[72];
    typedef unsigned (*arr36)[36];
    arr68 Qstage = (arr68)smraw;
    arr68 Ks = (arr68)(smraw + SM_KS);
    arr72 Vs = (arr72)(smraw + SM_VS);
    arr36 Ps = (arr36)(smraw + SM_PS);

    const int bh = blockIdx.y;
    const int qt = gridDim.x - 1 - (int)blockIdx.x;
    const int q0 = qt * 128;
    const int tid = threadIdx.x;
    const int warp = tid >> 5, lane = tid & 31;
    const int gid = lane >> 2, tig = lane & 3;
    const int w32 = warp * 32;

    const float* Qg = g_q + ((size_t)bh * Ss + q0) * HD;
#pragma unroll
    for (int i = 0; i < 16; i++) {
        const int idx = tid + i * 128;
        const int r = idx >> 4, c = (idx & 15) * 4;
        float4 a = *(const float4*)(Qg + r * HD + c);
        uint4 u = { f2tf(a.x * 0.125f), f2tf(a.y * 0.125f),
                    f2tf(a.z * 0.125f), f2tf(a.w * 0.125f) };
        *(uint4*)&Qstage[r][c] = u;
    }
    __syncthreads();

    unsigned qf[8][2][4];
#pragma unroll
    for (int kk = 0; kk < 8; kk++) {
        const int kb = kk * 8;
#pragma unroll
        for (int mf = 0; mf < 2; mf++) {
            const int rb = w32 + mf * 16 + gid;
            qf[kk][mf][0] = Qstage[rb    ][kb + tig];
            qf[kk][mf][1] = Qstage[rb + 8][kb + tig];
            qf[kk][mf][2] = Qstage[rb    ][kb + tig + 4];
            qf[kk][mf][3] = Qstage[rb + 8][kb + tig + 4];
        }
    }
    __syncthreads();

    float o[2][8][4] = {};
    float m[2][2] = { {-1e30f,-1e30f}, {-1e30f,-1e30f} };
    float l[2][2] = { {0.f,0.f}, {0.f,0.f} };

    const int nkt = (q0 + 128) / 32;

    float4 rk[4], rv[4];
#pragma unroll
    for (int i = 0; i < 4; i++) {
        const int idx = tid + i * 128;
        const int r = idx >> 4, c = (idx & 15) * 4;
        rk[i] = *(const float4*)(g_k + ((size_t)bh * Ss + r) * HD + c);
        rv[i] = *(const float4*)(g_v + ((size_t)bh * Ss + r) * HD + c);
    }

    for (int kt = 0; kt < nkt; kt++) {
        const int k0 = kt * 32;
        __syncthreads();
#pragma unroll
        for (int i = 0; i < 4; i++) {
            const int idx = tid + i * 128;
            const int r = idx >> 4, c = (idx & 15) * 4;
            uint4 u = { f2tf(rk[i].x), f2tf(rk[i].y), f2tf(rk[i].z), f2tf(rk[i].w) };
            *(uint4*)&Ks[r][c] = u;
            uint4 v = { f2tf(rv[i].x), f2tf(rv[i].y), f2tf(rv[i].z), f2tf(rv[i].w) };
            *(uint4*)&Vs[r][c] = v;
        }
        __syncthreads();

        if (kt + 1 < nkt) {
            const int kn0 = k0 + 32;
#pragma unroll
            for (int i = 0; i < 4; i++) {
                const int idx = tid + i * 128;
                const int r = idx >> 4, c = (idx & 15) * 4;
                rk[i] = *(const float4*)(g_k + ((size_t)bh * Ss + kn0 + r) * HD + c);
                rv[i] = *(const float4*)(g_v + ((size_t)bh * Ss + kn0 + r) * HD + c);
            }
        }

        if (k0 <= q0 + w32 + 31) {
            float s[2][4][4] = {};
#pragma unroll
            for (int kk = 0; kk < 8; kk++) {
                const int kb = kk * 8;
#pragma unroll
                for (int nf = 0; nf < 4; nf++) {
                    const int cb = nf * 8 + gid;
                    unsigned b0 = Ks[cb][kb + tig];
                    unsigned b1 = Ks[cb][kb + tig + 4];
                    mma_tf32(s[0][nf], qf[kk][0][0], qf[kk][0][1],
                                       qf[kk][0][2], qf[kk][0][3], b0, b1);
                    mma_tf32(s[1][nf], qf[kk][1][0], qf[kk][1][1],
                                       qf[kk][1][2], qf[kk][1][3], b0, b1);
                }
            }

            if (k0 + 32 > q0 + w32) {
#pragma unroll
                for (int mf = 0; mf < 2; mf++) {
                    const int r0 = q0 + w32 + mf * 16 + gid, r1 = r0 + 8;
#pragma unroll
                    for (int nf = 0; nf < 4; nf++) {
                        const int cg = k0 + nf * 8 + 2 * tig;
                        if (cg     > r0) s[mf][nf][0] = -1e30f;
                        if (cg + 1 > r0) s[mf][nf][1] = -1e30f;
                        if (cg     > r1) s[mf][nf][2] = -1e30f;
                        if (cg + 1 > r1) s[mf][nf][3] = -1e30f;
                    }
                }
            }

#pragma unroll
            for (int mf = 0; mf < 2; mf++) {
                float t0 = -1e30f, t1 = -1e30f;
#pragma unroll
                for (int nf = 0; nf < 4; nf++) {
                    t0 = fmaxf(t0, fmaxf(s[mf][nf][0], s[mf][nf][1]));
                    t1 = fmaxf(t1, fmaxf(s[mf][nf][2], s[mf][nf][3]));
                }
                t0 = fmaxf(t0, __shfl_xor_sync(~0u, t0, 1));
                t0 = fmaxf(t0, __shfl_xor_sync(~0u, t0, 2));
                t1 = fmaxf(t1, __shfl_xor_sync(~0u, t1, 1));
                t1 = fmaxf(t1, __shfl_xor_sync(~0u, t1, 2));

                const float nm0 = fmaxf(m[mf][0], t0), nm1 = fmaxf(m[mf][1], t1);
                const float cr0 = __expf(m[mf][0] - nm0), cr1 = __expf(m[mf][1] - nm1);
                l[mf][0] *= cr0; l[mf][1] *= cr1;
#pragma unroll
                for (int nf = 0; nf < 8; nf++) {
                    o[mf][nf][0] *= cr0; o[mf][nf][1] *= cr0;
                    o[mf][nf][2] *= cr1; o[mf][nf][3] *= cr1;
                }
                m[mf][0] = nm0; m[mf][1] = nm1;

                float ls0 = 0.f, ls1 = 0.f;
#pragma unroll
                for (int nf = 0; nf < 4; nf++) {
                    const float p0 = __expf(s[mf][nf][0] - nm0);
                    const float p1 = __expf(s[mf][nf][1] - nm0);
                    const float p2 = __expf(s[mf][nf][2] - nm1);
                    const float p3 = __expf(s[mf][nf][3] - nm1);
                    ls0 += p0 + p1; ls1 += p2 + p3;
                    uint2 w01 = { f2tf(p0), f2tf(p1) };
                    uint2 w23 = { f2tf(p2), f2tf(p3) };
                    const int rb = w32 + mf * 16 + gid;
                    *(uint2*)&Ps[rb    ][nf * 8 + 2 * tig] = w01;
                    *(uint2*)&Ps[rb + 8][nf * 8 + 2 * tig] = w23;
                }
                ls0 += __shfl_xor_sync(~0u, ls0, 1);
                ls0 += __shfl_xor_sync(~0u, ls0, 2);
                ls1 += __shfl_xor_sync(~0u, ls1, 1);
                ls1 += __shfl_xor_sync(~0u, ls1, 2);
                l[mf][0] += ls0; l[mf][1] += ls1;
            }

            __syncwarp();
#pragma unroll
            for (int kk = 0; kk < 4; kk++) {
                const int kb = kk * 8;
                unsigned af[2][4];
#pragma unroll
                for (int mf = 0; mf < 2; mf++) {
                    const int rb = w32 + mf * 16 + gid;
                    af[mf][0] = Ps[rb    ][kb + tig];
                    af[mf][1] = Ps[rb + 8][kb + tig];
                    af[mf][2] = Ps[rb    ][kb + tig + 4];
                    af[mf][3] = Ps[rb + 8][kb + tig + 4];
                }
#pragma unroll
                for (int nf = 0; nf < 8; nf++) {
                    const int cb = nf * 8 + gid;
                    unsigned b0 = Vs[kb + tig    ][cb];
                    unsigned b1 = Vs[kb + tig + 4][cb];
                    mma_tf32(o[0][nf], af[0][0], af[0][1], af[0][2], af[0][3], b0, b1);
                    mma_tf32(o[1][nf], af[1][0], af[1][1], af[1][2], af[1][3], b0, b1);
                }
            }
        }
    }

#pragma unroll
    for (int mf = 0; mf < 2; mf++) {
        const float inv0 = 1.f / l[mf][0], inv1 = 1.f / l[mf][1];
        float* O0 = g_ao + ((size_t)bh * Ss + q0 + w32 + mf * 16 + gid) * HD;
        float* O1 = O0 + 8 * HD;
#pragma unroll
        for (int nf = 0; nf < 8; nf++) {
            const int cg = nf * 8 + 2 * tig;
            O0[cg]     = o[mf][nf][0] * inv0;
            O0[cg + 1] = o[mf][nf][1] * inv0;
            O1[cg]     = o[mf][nf][2] * inv1;
            O1[cg + 1] = o[mf][nf][3] * inv1;
        }
    }
}

// ---------------------------------------------------------------------------
// Kernel 3: output projection, same v3 GEMM core, A gathered from head layout.
// ---------------------------------------------------------------------------
__global__ void __launch_bounds__(256, 1) proj_gemm(const float* __restrict__ Wp,
                                                    const float* __restrict__ bias,
                                                    float* __restrict__ out)
{
    __shared__ unsigned As[2][256][12];
    __shared__ unsigned Bs[2][8][132];

    const int tid  = threadIdx.x;
    const int warp = tid >> 5, lane = tid & 31;
    const int wm = warp & 3, wn = warp >> 2;
    const int gid = lane >> 2, tig = lane & 3;
    const int bm = blockIdx.y * 256, bn = blockIdx.x * 128;

    const int ar0 = tid >> 1,         ac0 = (tid & 1) * 4;
    const int ar1 = (tid + 256) >> 1, ac1 = ((tid + 256) & 1) * 4;
    const int brow = tid >> 5, bcn = (tid & 31) * 4;

    const int m0r = bm + ar0;
    const int b0i = m0r / Ss, s0i = m0r % Ss;
    const int m1r = bm + ar1;
    const int b1i = m1r / Ss, s1i = m1r % Ss;

    float acc[4][8][4] = {};
    float4 ra0, ra1, rb0;

    {
        const int k0a = ac0, k1a = ac1;
        ra0 = *(const float4*)(g_ao + ((size_t)(b0i * Hh + (k0a >> 6)) * Ss + s0i) * HD + (k0a & 63));
        ra1 = *(const float4*)(g_ao + ((size_t)(b1i * Hh + (k1a >> 6)) * Ss + s1i) * HD + (k1a & 63));
    }
    rb0 = *(const float4*)(Wp + (size_t)brow * Dd + bn + bcn);
    {
        uint4 u0 = { f2tf(ra0.x), f2tf(ra0.y), f2tf(ra0.z), f2tf(ra0.w) };
        uint4 u1 = { f2tf(ra1.x), f2tf(ra1.y), f2tf(ra1.z), f2tf(ra1.w) };
        *(uint4*)&As[0][ar0][ac0] = u0;
        *(uint4*)&As[0][ar1][ac1] = u1;
        uint4 v0 = { f2tf(rb0.x), f2tf(rb0.y), f2tf(rb0.z), f2tf(rb0.w) };
        *(uint4*)&Bs[0][brow][bcn] = v0;
    }
    __syncthreads();

    int cur = 0;
    for (int k0 = 0; k0 < Dd; k0 += 8) {
        const int kn = k0 + 8;
        if (kn < Dd) {
            const int k0a = kn + ac0, k1a = kn + ac1;
            ra0 = *(const float4*)(g_ao + ((size_t)(b0i * Hh + (k0a >> 6)) * Ss + s0i) * HD + (k0a & 63));
            ra1 = *(const float4*)(g_ao + ((size_t)(b1i * Hh + (k1a >> 6)) * Ss + s1i) * HD + (k1a & 63));
            rb0 = *(const float4*)(Wp + (size_t)(kn + brow) * Dd + bn + bcn);
        }

        unsigned af[4][4];
#pragma unroll
        for (int mf = 0; mf < 4; mf++) {
            const int rb = wm * 64 + mf * 16 + gid;
            af[mf][0] = As[cur][rb    ][tig];
            af[mf][1] = As[cur][rb + 8][tig];
            af[mf][2] = As[cur][rb    ][tig + 4];
            af[mf][3] = As[cur][rb + 8][tig + 4];
        }
#pragma unroll
        for (int nf = 0; nf < 8; nf++) {
            const int cb = wn * 64 + nf * 8 + gid;
            unsigned b0 = Bs[cur][tig    ][cb];
            unsigned b1 = Bs[cur][tig + 4][cb];
#pragma unroll
            for (int mf = 0; mf < 4; mf++)
                mma_tf32(acc[mf][nf], af[mf][0], af[mf][1], af[mf][2], af[mf][3], b0, b1);
        }

        if (kn < Dd) {
            const int nxt = cur ^ 1;
            uint4 u0 = { f2tf(ra0.x), f2tf(ra0.y), f2tf(ra0.z), f2tf(ra0.w) };
            uint4 u1 = { f2tf(ra1.x), f2tf(ra1.y), f2tf(ra1.z), f2tf(ra1.w) };
            *(uint4*)&As[nxt][ar0][ac0] = u0;
            *(uint4*)&As[nxt][ar1][ac1] = u1;
            uint4 v0 = { f2tf(rb0.x), f2tf(rb0.y), f2tf(rb0.z), f2tf(rb0.w) };
            *(uint4*)&Bs[nxt][brow][bcn] = v0;
            __syncthreads();
            cur = nxt;
        }
    }

#pragma unroll
    for (int mf = 0; mf < 4; mf++) {
#pragma unroll
        for (int nf = 0; nf < 8; nf++) {
            const int ncol = wn * 64 + nf * 8 + 2 * tig;
            const float bi0 = bias[bn + ncol], bi1 = bias[bn + ncol + 1];
#pragma unroll
            for (int rr = 0; rr < 2; rr++) {
                const int m = bm + wm * 64 + mf * 16 + gid + rr * 8;
                out[(size_t)m * Dd + bn + ncol]     = acc[mf][nf][rr * 2]     + bi0;
                out[(size_t)m * Dd + bn + ncol + 1] = acc[mf][nf][rr * 2 + 1] + bi1;
            }
        }
    }
}

// ---------------------------------------------------------------------------
extern "C" void kernel_launch(void* const* d_in, const int* in_sizes, int n_in,
                              void* d_out, int out_size)
{
    const float* hs  = (const float*)d_in[0];   // hidden_states [B,S,D]
    const float* caw = (const float*)d_in[1];   // c_attn_w [D,3D]
    const float* cab = (const float*)d_in[2];   // c_attn_b [3D]
    const float* cpw = (const float*)d_in[3];   // c_proj_w [D,D]
    const float* cpb = (const float*)d_in[4];   // c_proj_b [D]
    float* out = (float*)d_out;                 // [B,S,D] fp32

    qkv_gemm<<<dim3(N3 / 128, Mm / 256), 256>>>(hs, caw, cab);
    attn_mma<<<dim3(Ss / 128, Bb * Hh), 128>>>();
    proj_gemm<<<dim3(Dd / 128, Mm / 256), 256>>>(cpw, cpb, out);
}

// round 10
// speedup vs baseline: 1.2887x; 1.2887x over previous
#include <cuda_runtime.h>
#include <math.h>

#define Bb 2
#define Ss 2048
#define Dd 1024
#define Hh 16
#define HD 64
#define Mm (Bb*Ss)      /* 4096 */
#define N3 (3*Dd)       /* 3072 */

// Scratch.
__device__ float g_q [Bb*Hh*Ss*HD];
__device__ float g_k [Bb*Hh*Ss*HD];   // stored tf32-rounded by qkv epilogue
__device__ float g_v [Bb*Hh*Ss*HD];   // stored tf32-rounded by qkv epilogue
__device__ float g_ao[Bb*Hh*Ss*HD];   // stored tf32-rounded by attn epilogue
__device__ float g_xr [Mm*Dd];        // X  tf32-rounded
__device__ float g_wr [Dd*N3];        // W  tf32-rounded
__device__ float g_wpr[Dd*Dd];        // Wp tf32-rounded

__device__ __forceinline__ unsigned f2tf(float x) {
    unsigned y;
    asm("cvt.rna.tf32.f32 %0, %1;" : "=r"(y) : "f"(x));
    return y;
}
__device__ __forceinline__ float f2tff(float x) {
    return __uint_as_float(f2tf(x));
}

__device__ __forceinline__ void mma_tf32(float c[4],
                                         unsigned a0, unsigned a1, unsigned a2, unsigned a3,
                                         unsigned b0, unsigned b1) {
    asm volatile(
        "mma.sync.aligned.m16n8k8.row.col.f32.tf32.tf32.f32 "
        "{%0,%1,%2,%3},{%4,%5,%6,%7},{%8,%9},{%0,%1,%2,%3};\n"
        : "+f"(c[0]), "+f"(c[1]), "+f"(c[2]), "+f"(c[3])
        : "r"(a0), "r"(a1), "r"(a2), "r"(a3), "r"(b0), "r"(b1));
}

__device__ __forceinline__ void cpa16(void* smem, const void* gmem) {
    unsigned sa = (unsigned)__cvta_generic_to_shared(smem);
    asm volatile("cp.async.cg.shared.global [%0], [%1], 16;" :: "r"(sa), "l"(gmem));
}
#define CPA_COMMIT() asm volatile("cp.async.commit_group;")
#define CPA_WAIT0()  asm volatile("cp.async.wait_group 0;")
#define CPA_WAIT1()  asm volatile("cp.async.wait_group 1;")

// ---------------------------------------------------------------------------
// Kernel 0: elementwise tf32-round copy (prepass for X, W, Wp).
// ---------------------------------------------------------------------------
__global__ void __launch_bounds__(256) round_copy(const float* __restrict__ src,
                                                  float* __restrict__ dst, int n4)
{
    const int i = blockIdx.x * 256 + threadIdx.x;
    if (i < n4) {
        float4 a = ((const float4*)src)[i];
        float4 r = { f2tff(a.x), f2tff(a.y), f2tff(a.z), f2tff(a.w) };
        ((float4*)dst)[i] = r;
    }
}

// ===========================================================================
// GEMM core (R8 shape): BM=128, BN=128, BK=16, 256 thr, 8 warps, warp 32x64.
// cp.async double-buffered: inputs pre-rounded -> no cvt, no LDG/STS regs.
// ===========================================================================

__global__ void __launch_bounds__(256, 2) qkv_gemm(const float* __restrict__ bias)
{
    __shared__ unsigned As[2][128][20];
    __shared__ unsigned Bs[2][16][136];

    const int tid  = threadIdx.x;
    const int warp = tid >> 5, lane = tid & 31;
    const int wm = warp & 3, wn = warp >> 2;
    const int gid = lane >> 2, tig = lane & 3;
    const int bm = blockIdx.y * 128, bn = blockIdx.x * 128;

    const int arow = tid >> 2, acg = (tid & 3) * 4;
    const int brow = tid >> 5, bcn = (tid & 31) * 4;

    const float* Xa0 = g_xr + (size_t)(bm + arow)      * Dd + acg;
    const float* Xa1 = g_xr + (size_t)(bm + arow + 64) * Dd + acg;
    const float* Wb0 = g_wr + (size_t)(brow)     * N3 + bn + bcn;
    const float* Wb1 = g_wr + (size_t)(brow + 8) * N3 + bn + bcn;

    float acc[2][8][4] = {};

    // prologue: tile 0
    cpa16(&As[0][arow     ][acg], Xa0);
    cpa16(&As[0][arow + 64][acg], Xa1);
    cpa16(&Bs[0][brow    ][bcn], Wb0);
    cpa16(&Bs[0][brow + 8][bcn], Wb1);
    CPA_COMMIT();

    int cur = 0;
    for (int k0 = 0; k0 < Dd; k0 += 16) {
        const int kn = k0 + 16;
        if (kn < Dd) {
            const int nxt = cur ^ 1;
            cpa16(&As[nxt][arow     ][acg], Xa0 + kn);
            cpa16(&As[nxt][arow + 64][acg], Xa1 + kn);
            cpa16(&Bs[nxt][brow    ][bcn], Wb0 + (size_t)kn * N3);
            cpa16(&Bs[nxt][brow + 8][bcn], Wb1 + (size_t)kn * N3);
            CPA_COMMIT();
            CPA_WAIT1();
        } else {
            CPA_WAIT0();
        }
        __syncthreads();

#pragma unroll
        for (int ks = 0; ks < 2; ks++) {
            const int kb = ks * 8;
            unsigned af[2][4];
#pragma unroll
            for (int mf = 0; mf < 2; mf++) {
                const int rb = wm * 32 + mf * 16 + gid;
                af[mf][0] = As[cur][rb    ][kb + tig];
                af[mf][1] = As[cur][rb + 8][kb + tig];
                af[mf][2] = As[cur][rb    ][kb + tig + 4];
                af[mf][3] = As[cur][rb + 8][kb + tig + 4];
            }
#pragma unroll
            for (int nf = 0; nf < 8; nf++) {
                const int cb = wn * 64 + nf * 8 + gid;
                unsigned b0 = Bs[cur][kb + tig    ][cb];
                unsigned b1 = Bs[cur][kb + tig + 4][cb];
                mma_tf32(acc[0][nf], af[0][0], af[0][1], af[0][2], af[0][3], b0, b1);
                mma_tf32(acc[1][nf], af[1][0], af[1][1], af[1][2], af[1][3], b0, b1);
            }
        }
        __syncthreads();   // all reads of buf[cur] done before next iter overwrites it
        cur ^= 1;
    }

    // Epilogue: bias + scatter; k/v stored tf32-rounded (q raw, scaled later).
    const int which = bn / Dd;
    const int hbase = (bn % Dd) / HD;
    float* dst = (which == 0) ? g_q : ((which == 1) ? g_k : g_v);
    const float* bb = bias;
#pragma unroll
    for (int mf = 0; mf < 2; mf++) {
#pragma unroll
        for (int nf = 0; nf < 8; nf++) {
            const int ncol = wn * 64 + nf * 8 + 2 * tig;
            const int h = hbase + (ncol >> 6);
            const int dd = ncol & 63;
            const float bi0 = bb[bn + ncol], bi1 = bb[bn + ncol + 1];
#pragma unroll
            for (int rr = 0; rr < 2; rr++) {
                const int m = bm + wm * 32 + mf * 16 + gid + rr * 8;
                const int b = m / Ss, s = m % Ss;
                float* drow = dst + ((size_t)(b * Hh + h) * Ss + s) * HD;
                float v0 = acc[mf][nf][rr * 2]     + bi0;
                float v1 = acc[mf][nf][rr * 2 + 1] + bi1;
                if (which != 0) { v0 = f2tff(v0); v1 = f2tff(v1); }
                drow[dd]     = v0;
                drow[dd + 1] = v1;
            }
        }
    }
}

// ---------------------------------------------------------------------------
// Kernel 2: causal flash attention (R8 structure; K/V staging is a raw copy
// since g_k/g_v are pre-rounded).
// ---------------------------------------------------------------------------
#define SM_KS 0
#define SM_VS (32*68*4)                    /* 8704  */
#define SM_PS (SM_VS + 32*72*4)            /* 17920 */
#define SM_TOT (SM_PS + 128*36*4)          /* 36352 */

__global__ void __launch_bounds__(128, 2) attn_mma()
{
    __shared__ __align__(16) unsigned char smraw[SM_TOT];
    typedef unsigned (*arr68)[68];
    typedef unsigned (*arr72)[72];
    typedef unsigned (*arr36)[36];
    arr68 Qstage = (arr68)smraw;
    arr68 Ks = (arr68)(smraw + SM_KS);
    arr72 Vs = (arr72)(smraw + SM_VS);
    arr36 Ps = (arr36)(smraw + SM_PS);

    const int bh = blockIdx.y;
    const int qt = gridDim.x - 1 - (int)blockIdx.x;
    const int q0 = qt * 128;
    const int tid = threadIdx.x;
    const int warp = tid >> 5, lane = tid & 31;
    const int gid = lane >> 2, tig = lane & 3;
    const int w32 = warp * 32;

    const float* Qg = g_q + ((size_t)bh * Ss + q0) * HD;
#pragma unroll
    for (int i = 0; i < 16; i++) {
        const int idx = tid + i * 128;
        const int r = idx >> 4, c = (idx & 15) * 4;
        float4 a = *(const float4*)(Qg + r * HD + c);
        uint4 u = { f2tf(a.x * 0.125f), f2tf(a.y * 0.125f),
                    f2tf(a.z * 0.125f), f2tf(a.w * 0.125f) };
        *(uint4*)&Qstage[r][c] = u;
    }
    __syncthreads();

    unsigned qf[8][2][4];
#pragma unroll
    for (int kk = 0; kk < 8; kk++) {
        const int kb = kk * 8;
#pragma unroll
        for (int mf = 0; mf < 2; mf++) {
            const int rb = w32 + mf * 16 + gid;
            qf[kk][mf][0] = Qstage[rb    ][kb + tig];
            qf[kk][mf][1] = Qstage[rb + 8][kb + tig];
            qf[kk][mf][2] = Qstage[rb    ][kb + tig + 4];
            qf[kk][mf][3] = Qstage[rb + 8][kb + tig + 4];
        }
    }
    __syncthreads();

    float o[2][8][4] = {};
    float m[2][2] = { {-1e30f,-1e30f}, {-1e30f,-1e30f} };
    float l[2][2] = { {0.f,0.f}, {0.f,0.f} };

    const int nkt = (q0 + 128) / 32;

    uint4 rk[4], rv[4];
#pragma unroll
    for (int i = 0; i < 4; i++) {
        const int idx = tid + i * 128;
        const int r = idx >> 4, c = (idx & 15) * 4;
        rk[i] = *(const uint4*)(g_k + ((size_t)bh * Ss + r) * HD + c);
        rv[i] = *(const uint4*)(g_v + ((size_t)bh * Ss + r) * HD + c);
    }

    for (int kt = 0; kt < nkt; kt++) {
        const int k0 = kt * 32;
        __syncthreads();
#pragma unroll
        for (int i = 0; i < 4; i++) {
            const int idx = tid + i * 128;
            const int r = idx >> 4, c = (idx & 15) * 4;
            *(uint4*)&Ks[r][c] = rk[i];          // pre-rounded: raw copy
            *(uint4*)&Vs[r][c] = rv[i];
        }
        __syncthreads();

        if (kt + 1 < nkt) {
            const int kn0 = k0 + 32;
#pragma unroll
            for (int i = 0; i < 4; i++) {
                const int idx = tid + i * 128;
                const int r = idx >> 4, c = (idx & 15) * 4;
                rk[i] = *(const uint4*)(g_k + ((size_t)bh * Ss + kn0 + r) * HD + c);
                rv[i] = *(const uint4*)(g_v + ((size_t)bh * Ss + kn0 + r) * HD + c);
            }
        }

        if (k0 <= q0 + w32 + 31) {
            float s[2][4][4] = {};
#pragma unroll
            for (int kk = 0; kk < 8; kk++) {
                const int kb = kk * 8;
#pragma unroll
                for (int nf = 0; nf < 4; nf++) {
                    const int cb = nf * 8 + gid;
                    unsigned b0 = Ks[cb][kb + tig];
                    unsigned b1 = Ks[cb][kb + tig + 4];
                    mma_tf32(s[0][nf], qf[kk][0][0], qf[kk][0][1],
                                       qf[kk][0][2], qf[kk][0][3], b0, b1);
                    mma_tf32(s[1][nf], qf[kk][1][0], qf[kk][1][1],
                                       qf[kk][1][2], qf[kk][1][3], b0, b1);
                }
            }

            if (k0 + 32 > q0 + w32) {
#pragma unroll
                for (int mf = 0; mf < 2; mf++) {
                    const int r0 = q0 + w32 + mf * 16 + gid, r1 = r0 + 8;
#pragma unroll
                    for (int nf = 0; nf < 4; nf++) {
                        const int cg = k0 + nf * 8 + 2 * tig;
                        if (cg     > r0) s[mf][nf][0] = -1e30f;
                        if (cg + 1 > r0) s[mf][nf][1] = -1e30f;
                        if (cg     > r1) s[mf][nf][2] = -1e30f;
                        if (cg + 1 > r1) s[mf][nf][3] = -1e30f;
                    }
                }
            }

#pragma unroll
            for (int mf = 0; mf < 2; mf++) {
                float t0 = -1e30f, t1 = -1e30f;
#pragma unroll
                for (int nf = 0; nf < 4; nf++) {
                    t0 = fmaxf(t0, fmaxf(s[mf][nf][0], s[mf][nf][1]));
                    t1 = fmaxf(t1, fmaxf(s[mf][nf][2], s[mf][nf][3]));
                }
                t0 = fmaxf(t0, __shfl_xor_sync(~0u, t0, 1));
                t0 = fmaxf(t0, __shfl_xor_sync(~0u, t0, 2));
                t1 = fmaxf(t1, __shfl_xor_sync(~0u, t1, 1));
                t1 = fmaxf(t1, __shfl_xor_sync(~0u, t1, 2));

                const float nm0 = fmaxf(m[mf][0], t0), nm1 = fmaxf(m[mf][1], t1);
                const float cr0 = __expf(m[mf][0] - nm0), cr1 = __expf(m[mf][1] - nm1);
                l[mf][0] *= cr0; l[mf][1] *= cr1;
#pragma unroll
                for (int nf = 0; nf < 8; nf++) {
                    o[mf][nf][0] *= cr0; o[mf][nf][1] *= cr0;
                    o[mf][nf][2] *= cr1; o[mf][nf][3] *= cr1;
                }
                m[mf][0] = nm0; m[mf][1] = nm1;

                float ls0 = 0.f, ls1 = 0.f;
#pragma unroll
                for (int nf = 0; nf < 4; nf++) {
                    const float p0 = __expf(s[mf][nf][0] - nm0);
                    const float p1 = __expf(s[mf][nf][1] - nm0);
                    const float p2 = __expf(s[mf][nf][2] - nm1);
                    const float p3 = __expf(s[mf][nf][3] - nm1);
                    ls0 += p0 + p1; ls1 += p2 + p3;
                    uint2 w01 = { f2tf(p0), f2tf(p1) };
                    uint2 w23 = { f2tf(p2), f2tf(p3) };
                    const int rb = w32 + mf * 16 + gid;
                    *(uint2*)&Ps[rb    ][nf * 8 + 2 * tig] = w01;
                    *(uint2*)&Ps[rb + 8][nf * 8 + 2 * tig] = w23;
                }
                ls0 += __shfl_xor_sync(~0u, ls0, 1);
                ls0 += __shfl_xor_sync(~0u, ls0, 2);
                ls1 += __shfl_xor_sync(~0u, ls1, 1);
                ls1 += __shfl_xor_sync(~0u, ls1, 2);
                l[mf][0] += ls0; l[mf][1] += ls1;
            }

            __syncwarp();
#pragma unroll
            for (int kk = 0; kk < 4; kk++) {
                const int kb = kk * 8;
                unsigned af[2][4];
#pragma unroll
                for (int mf = 0; mf < 2; mf++) {
                    const int rb = w32 + mf * 16 + gid;
                    af[mf][0] = Ps[rb    ][kb + tig];
                    af[mf][1] = Ps[rb + 8][kb + tig];
                    af[mf][2] = Ps[rb    ][kb + tig + 4];
                    af[mf][3] = Ps[rb + 8][kb + tig + 4];
                }
#pragma unroll
                for (int nf = 0; nf < 8; nf++) {
                    const int cb = nf * 8 + gid;
                    unsigned b0 = Vs[kb + tig    ][cb];
                    unsigned b1 = Vs[kb + tig + 4][cb];
                    mma_tf32(o[0][nf], af[0][0], af[0][1], af[0][2], af[0][3], b0, b1);
                    mma_tf32(o[1][nf], af[1][0], af[1][1], af[1][2], af[1][3], b0, b1);
                }
            }
        }
    }

    // store AO tf32-rounded (proj reads it raw via cp.async)
#pragma unroll
    for (int mf = 0; mf < 2; mf++) {
        const float inv0 = 1.f / l[mf][0], inv1 = 1.f / l[mf][1];
        float* O0 = g_ao + ((size_t)bh * Ss + q0 + w32 + mf * 16 + gid) * HD;
        float* O1 = O0 + 8 * HD;
#pragma unroll
        for (int nf = 0; nf < 8; nf++) {
            const int cg = nf * 8 + 2 * tig;
            O0[cg]     = f2tff(o[mf][nf][0] * inv0);
            O0[cg + 1] = f2tff(o[mf][nf][1] * inv0);
            O1[cg]     = f2tff(o[mf][nf][2] * inv1);
            O1[cg + 1] = f2tff(o[mf][nf][3] * inv1);
        }
    }
}

// ---------------------------------------------------------------------------
// Kernel 3: output projection, cp.async double-buffered (A=g_ao pre-rounded,
// B=g_wpr pre-rounded).
// ---------------------------------------------------------------------------
__global__ void __launch_bounds__(256, 2) proj_gemm(const float* __restrict__ bias,
                                                    float* __restrict__ out)
{
    __shared__ unsigned As[2][128][20];
    __shared__ unsigned Bs[2][16][136];

    const int tid  = threadIdx.x;
    const int warp = tid >> 5, lane = tid & 31;
    const int wm = warp & 3, wn = warp >> 2;
    const int gid = lane >> 2, tig = lane & 3;
    const int bm = blockIdx.y * 128, bn = blockIdx.x * 128;

    const int arow = tid >> 2, acg = (tid & 3) * 4;
    const int brow = tid >> 5, bcn = (tid & 31) * 4;

    const int m0r = bm + arow;
    const int b0i = m0r / Ss, s0i = m0r % Ss;
    const int m1r = bm + arow + 64;
    const int b1i = m1r / Ss, s1i = m1r % Ss;

    float acc[2][8][4] = {};

    // A gather base (head layout); k-chunk of 4 stays within one head
    const float* A0base = g_ao + (size_t)(b0i * Hh) * Ss * HD + (size_t)s0i * HD;
    const float* A1base = g_ao + (size_t)(b1i * Hh) * Ss * HD + (size_t)s1i * HD;
    const float* Wb0 = g_wpr + (size_t)(brow)     * Dd + bn + bcn;
    const float* Wb1 = g_wpr + (size_t)(brow + 8) * Dd + bn + bcn;

    {
        const int k = acg, h = k >> 6, dd = k & 63;
        cpa16(&As[0][arow     ][acg], A0base + (size_t)h * Ss * HD + dd);
        cpa16(&As[0][arow + 64][acg], A1base + (size_t)h * Ss * HD + dd);
        cpa16(&Bs[0][brow    ][bcn], Wb0);
        cpa16(&Bs[0][brow + 8][bcn], Wb1);
        CPA_COMMIT();
    }

    int cur = 0;
    for (int k0 = 0; k0 < Dd; k0 += 16) {
        const int kn = k0 + 16;
        if (kn < Dd) {
            const int nxt = cur ^ 1;
            const int k = kn + acg, h = k >> 6, dd = k & 63;
            cpa16(&As[nxt][arow     ][acg], A0base + (size_t)h * Ss * HD + dd);
            cpa16(&As[nxt][arow + 64][acg], A1base + (size_t)h * Ss * HD + dd);
            cpa16(&Bs[nxt][brow    ][bcn], Wb0 + (size_t)kn * Dd);
            cpa16(&Bs[nxt][brow + 8][bcn], Wb1 + (size_t)kn * Dd);
            CPA_COMMIT();
            CPA_WAIT1();
        } else {
            CPA_WAIT0();
        }
        __syncthreads();

#pragma unroll
        for (int ks = 0; ks < 2; ks++) {
            const int kb = ks * 8;
            unsigned af[2][4];
#pragma unroll
            for (int mf = 0; mf < 2; mf++) {
                const int rb = wm * 32 + mf * 16 + gid;
                af[mf][0] = As[cur][rb    ][kb + tig];
                af[mf][1] = As[cur][rb + 8][kb + tig];
                af[mf][2] = As[cur][rb    ][kb + tig + 4];
                af[mf][3] = As[cur][rb + 8][kb + tig + 4];
            }
#pragma unroll
            for (int nf = 0; nf < 8; nf++) {
                const int cb = wn * 64 + nf * 8 + gid;
                unsigned b0 = Bs[cur][kb + tig    ][cb];
                unsigned b1 = Bs[cur][kb + tig + 4][cb];
                mma_tf32(acc[0][nf], af[0][0], af[0][1], af[0][2], af[0][3], b0, b1);
                mma_tf32(acc[1][nf], af[1][0], af[1][1], af[1][2], af[1][3], b0, b1);
            }
        }
        __syncthreads();
        cur ^= 1;
    }

#pragma unroll
    for (int mf = 0; mf < 2; mf++) {
#pragma unroll
        for (int nf = 0; nf < 8; nf++) {
            const int ncol = wn * 64 + nf * 8 + 2 * tig;
            const float bi0 = bias[bn + ncol], bi1 = bias[bn + ncol + 1];
#pragma unroll
            for (int rr = 0; rr < 2; rr++) {
                const int m = bm + wm * 32 + mf * 16 + gid + rr * 8;
                out[(size_t)m * Dd + bn + ncol]     = acc[mf][nf][rr * 2]     + bi0;
                out[(size_t)m * Dd + bn + ncol + 1] = acc[mf][nf][rr * 2 + 1] + bi1;
            }
        }
    }
}

// ---------------------------------------------------------------------------
extern "C" void kernel_launch(void* const* d_in, const int* in_sizes, int n_in,
                              void* d_out, int out_size)
{
    const float* hs  = (const float*)d_in[0];   // hidden_states [B,S,D]
    const float* caw = (const float*)d_in[1];   // c_attn_w [D,3D]
    const float* cab = (const float*)d_in[2];   // c_attn_b [3D]
    const float* cpw = (const float*)d_in[3];   // c_proj_w [D,D]
    const float* cpb = (const float*)d_in[4];   // c_proj_b [D]
    float* out = (float*)d_out;                 // [B,S,D] fp32

    float *xr, *wr, *wpr;
    cudaGetSymbolAddress((void**)&xr,  g_xr);
    cudaGetSymbolAddress((void**)&wr,  g_wr);
    cudaGetSymbolAddress((void**)&wpr, g_wpr);

    round_copy<<<(Mm*Dd/4 + 255)/256, 256>>>(hs,  xr,  Mm*Dd/4);
    round_copy<<<(Dd*N3/4 + 255)/256, 256>>>(caw, wr,  Dd*N3/4);
    round_copy<<<(Dd*Dd/4 + 255)/256, 256>>>(cpw, wpr, Dd*Dd/4);

    qkv_gemm<<<dim3(N3 / 128, Mm / 128), 256>>>(cab);
    attn_mma<<<dim3(Ss / 128, Bb * Hh), 128>>>();
    proj_gemm<<<dim3(Dd / 128, Mm / 128), 256>>>(cpb, out);
}

// round 15
// speedup vs baseline: 1.2983x; 1.0075x over previous
#include <cuda_runtime.h>
#include <math.h>
#include <stdint.h>

#define Bb 2
#define Ss 2048
#define Dd 1024
#define Hh 16
#define HD 64
#define Mm (Bb*Ss)      /* 4096 */
#define N3 (3*Dd)       /* 3072 */

// Scratch.
__device__ float g_q   [Bb*Hh*Ss*HD];
__device__ float g_k   [Bb*Hh*Ss*HD];   // tf32-rounded by qkv epilogue
__device__ float g_v   [Bb*Hh*Ss*HD];   // tf32-rounded by qkv epilogue
__device__ float g_ao  [Bb*Hh*Ss*HD];   // tf32-rounded by attn epilogue
__device__ float g_xr  [Mm*Dd];         // X tf32-rounded  [m][k]
__device__ float g_wrt [N3*Dd];         // W^T  [n][k] tf32-rounded
__device__ float g_wprt[Dd*Dd];         // Wp^T [n][k] tf32-rounded

__device__ __forceinline__ unsigned f2tf(float x) {
    unsigned y; asm("cvt.rna.tf32.f32 %0, %1;" : "=r"(y) : "f"(x)); return y;
}
__device__ __forceinline__ float f2tff(float x) { return __uint_as_float(f2tf(x)); }

__device__ __forceinline__ unsigned smem_u32(const void* p) {
    return (unsigned)__cvta_generic_to_shared(p);
}
__device__ __forceinline__ void cpa16(void* smem, const void* gmem) {
    asm volatile("cp.async.cg.shared.global [%0], [%1], 16;"
                 :: "r"(smem_u32(smem)), "l"(gmem));
}
#define CPA_COMMIT() asm volatile("cp.async.commit_group;")
#define CPA_WAIT0()  asm volatile("cp.async.wait_group 0;")
#define CPA_WAIT1()  asm volatile("cp.async.wait_group 1;")
#define CPA_WAIT2()  asm volatile("cp.async.wait_group 2;")

__device__ __forceinline__ void mma_tf32(float c[4],
                                         unsigned a0, unsigned a1, unsigned a2, unsigned a3,
                                         unsigned b0, unsigned b1) {
    asm volatile(
        "mma.sync.aligned.m16n8k8.row.col.f32.tf32.tf32.f32 "
        "{%0,%1,%2,%3},{%4,%5,%6,%7},{%8,%9},{%0,%1,%2,%3};\n"
        : "+f"(c[0]), "+f"(c[1]), "+f"(c[2]), "+f"(c[3])
        : "r"(a0), "r"(a1), "r"(a2), "r"(a3), "r"(b0), "r"(b1));
}

__device__ __forceinline__ void ldsm4(unsigned& r0, unsigned& r1,
                                      unsigned& r2, unsigned& r3, unsigned addr) {
    asm volatile("ldmatrix.sync.aligned.m8n8.x4.shared.b16 {%0,%1,%2,%3}, [%4];"
                 : "=r"(r0), "=r"(r1), "=r"(r2), "=r"(r3) : "r"(addr));
}

// ---------------------------------------------------------------------------
// Prepass kernels.
// ---------------------------------------------------------------------------
__global__ void __launch_bounds__(256) round_copy(const float* __restrict__ src,
                                                  float* __restrict__ dst, int n4)
{
    const int i = blockIdx.x * 256 + threadIdx.x;
    if (i < n4) {
        float4 a = ((const float4*)src)[i];
        float4 r = { f2tff(a.x), f2tff(a.y), f2tff(a.z), f2tff(a.w) };
        ((float4*)dst)[i] = r;
    }
}

// src[R][C] -> dst[C][R], tf32-rounded.
__global__ void __launch_bounds__(256) round_transpose(const float* __restrict__ src,
                                                       float* __restrict__ dst,
                                                       int R, int C)
{
    __shared__ float t[32][33];
    const int bx = blockIdx.x * 32;   // C tile
    const int by = blockIdx.y * 32;   // R tile
    const int tx = threadIdx.x & 31, ty = threadIdx.x >> 5;
#pragma unroll
    for (int i = 0; i < 32; i += 8)
        t[ty + i][tx] = src[(size_t)(by + ty + i) * C + bx + tx];
    __syncthreads();
#pragma unroll
    for (int i = 0; i < 32; i += 8)
        dst[(size_t)(bx + ty + i) * R + by + tx] = f2tff(t[tx][ty + i]);
}

// ===========================================================================
// GEMM core v5: BM=128, BN=128, BK=16, 256 thr, 8 warps (wm=warp&3, wn=warp>>2),
// warp 32x64.  BOTH A and B staged [row][k] with pad 20 (A rows = m, B rows = n
// from the TRANSPOSED weight).  Fragments via ldmatrix.x4.  4-stage cp.async
// ring, ONE __syncthreads per iteration.
// Stage layout (bytes): A [128][20] @0 (10240), B [128][20] @10240; stride 20480.
// ===========================================================================
#define STG 20480
#define GEMM_DYN (4*STG)
#define NK (Dd/16)   /* 64 */

__device__ __forceinline__ void g_fill(char* dyn, int stageoff,
                                       const float* __restrict__ Ap, int strideA,
                                       const float* __restrict__ Bp, int tid)
{
#pragma unroll
    for (int i = 0; i < 2; i++) {
        const int idx = tid + i * 256;           // 512 chunks: 128 rows x 4
        const int row = idx >> 2, cw = (idx & 3) * 4;
        cpa16(dyn + stageoff + (row * 20 + cw) * 4, Ap + (size_t)row * strideA + cw);
    }
#pragma unroll
    for (int i = 0; i < 2; i++) {
        const int idx = tid + i * 256;
        const int row = idx >> 2, cw = (idx & 3) * 4;
        cpa16(dyn + stageoff + 10240 + (row * 20 + cw) * 4, Bp + (size_t)row * Dd + cw);
    }
}

// Per-thread ldmatrix base offsets (bytes within a stage), computed once.
// A mf-block matrices: 0=(rows+0,k0-3) 1=(rows+8,k0-3) 2=(rows+0,k4-7) 3=(rows+8,k4-7)
// B pair p matrices:   0=(n+0,k0-3)    1=(n+0,k4-7)    2=(n+8,k0-3)    3=(n+8,k4-7)
#define GEMM_FRAG_OFFS()                                                        \
    const int tg = lane >> 3, trow = lane & 7;                                  \
    unsigned aoff[2], boff[4];                                                  \
    {                                                                           \
        _Pragma("unroll")                                                       \
        for (int mf = 0; mf < 2; mf++) {                                        \
            const int row = wm * 32 + mf * 16 + (tg & 1) * 8 + trow;            \
            const int cw  = (tg >> 1) * 4;                                      \
            aoff[mf] = (row * 20 + cw) * 4;                                     \
        }                                                                       \
        _Pragma("unroll")                                                       \
        for (int p = 0; p < 4; p++) {                                           \
            const int row = wn * 64 + p * 16 + (tg >> 1) * 8 + trow;            \
            const int cw  = (tg & 1) * 4;                                       \
            boff[p] = 10240 + (row * 20 + cw) * 4;                              \
        }                                                                       \
    }

#define GEMM_COMPUTE_STAGE(stb)                                                 \
    _Pragma("unroll")                                                           \
    for (int ks = 0; ks < 2; ks++) {                                            \
        const unsigned kby = ks * 32;                                           \
        unsigned af[2][4];                                                      \
        ldsm4(af[0][0], af[0][1], af[0][2], af[0][3], (stb) + aoff[0] + kby);   \
        ldsm4(af[1][0], af[1][1], af[1][2], af[1][3], (stb) + aoff[1] + kby);   \
        unsigned bf[4][4];                                                      \
        _Pragma("unroll")                                                       \
        for (int p = 0; p < 4; p++)                                             \
            ldsm4(bf[p][0], bf[p][1], bf[p][2], bf[p][3], (stb) + boff[p] + kby); \
        _Pragma("unroll")                                                       \
        for (int p = 0; p < 4; p++) {                                           \
            mma_tf32(acc[0][2*p],   af[0][0], af[0][1], af[0][2], af[0][3], bf[p][0], bf[p][1]); \
            mma_tf32(acc[1][2*p],   af[1][0], af[1][1], af[1][2], af[1][3], bf[p][0], bf[p][1]); \
            mma_tf32(acc[0][2*p+1], af[0][0], af[0][1], af[0][2], af[0][3], bf[p][2], bf[p][3]); \
            mma_tf32(acc[1][2*p+1], af[1][0], af[1][1], af[1][2], af[1][3], bf[p][2], bf[p][3]); \
        }                                                                       \
    }

// ---------------------------------------------------------------------------
// Kernel 1: QKV GEMM.  C[M,3D] = X@W + b, scatter to q/k/v head layout.
// ---------------------------------------------------------------------------
__global__ void __launch_bounds__(256, 2) qkv_gemm(const float* __restrict__ bias)
{
    extern __shared__ char dyn[];
    const int tid  = threadIdx.x;
    const int warp = tid >> 5, lane = tid & 31;
    const int wm = warp & 3, wn = warp >> 2;
    const int gid = lane >> 2, tig = lane & 3;
    const int bm = blockIdx.y * 128, bn = blockIdx.x * 128;
    const unsigned smem_base = smem_u32(dyn);

    GEMM_FRAG_OFFS();

    const float* Ab0 = g_xr  + (size_t)bm * Dd;
    const float* Bb0 = g_wrt + (size_t)bn * Dd;

    float acc[2][8][4] = {};

    for (int kt = 0; kt < 3; kt++) {
        g_fill(dyn, kt * STG, Ab0 + kt * 16, Dd, Bb0 + kt * 16, tid);
        CPA_COMMIT();
    }

    for (int it = 0; it < NK; it++) {
        const int rem = (NK - 1) - it;
        if (rem >= 2) CPA_WAIT2(); else if (rem == 1) CPA_WAIT1(); else CPA_WAIT0();
        __syncthreads();
        const int ft = it + 3;
        if (ft < NK) {
            g_fill(dyn, (ft & 3) * STG, Ab0 + ft * 16, Dd, Bb0 + ft * 16, tid);
            CPA_COMMIT();
        }
        const unsigned stb = smem_base + (it & 3) * STG;
        GEMM_COMPUTE_STAGE(stb);
    }

    // Epilogue: bias + scatter into q/k/v head layout; k/v stored tf32-rounded.
    const int which = bn / Dd;
    const int hbase = (bn % Dd) / HD;
    float* dst = (which == 0) ? g_q : ((which == 1) ? g_k : g_v);
#pragma unroll
    for (int mf = 0; mf < 2; mf++) {
#pragma unroll
        for (int nf = 0; nf < 8; nf++) {
            const int ncol = wn * 64 + nf * 8 + 2 * tig;
            const int h = hbase + (ncol >> 6);
            const int dd = ncol & 63;
            const float bi0 = bias[bn + ncol], bi1 = bias[bn + ncol + 1];
#pragma unroll
            for (int rr = 0; rr < 2; rr++) {
                const int m = bm + wm * 32 + mf * 16 + gid + rr * 8;
                const int b = m / Ss, s = m % Ss;
                float* drow = dst + ((size_t)(b * Hh + h) * Ss + s) * HD;
                float v0 = acc[mf][nf][rr * 2]     + bi0;
                float v1 = acc[mf][nf][rr * 2 + 1] + bi1;
                if (which != 0) { v0 = f2tff(v0); v1 = f2tff(v1); }
                drow[dd]     = v0;
                drow[dd + 1] = v1;
            }
        }
    }
}

// ---------------------------------------------------------------------------
// Kernel 3: output projection.  out = AO@Wp + b; A gathered from head layout
// (k-chunk of 16 stays within one head: HD=64, k0 multiple of 16).
// ---------------------------------------------------------------------------
__global__ void __launch_bounds__(256, 2) proj_gemm(const float* __restrict__ bias,
                                                    float* __restrict__ out)
{
    extern __shared__ char dyn[];
    const int tid  = threadIdx.x;
    const int warp = tid >> 5, lane = tid & 31;
    const int wm = warp & 3, wn = warp >> 2;
    const int gid = lane >> 2, tig = lane & 3;
    const int bm = blockIdx.y * 128, bn = blockIdx.x * 128;
    const unsigned smem_base = smem_u32(dyn);
    const int b0 = bm / Ss, s0 = bm % Ss;   // M-tile within one batch (128 | 2048)

    GEMM_FRAG_OFFS();

    const float* Bb0 = g_wprt + (size_t)bn * Dd;

    float acc[2][8][4] = {};

    for (int kt = 0; kt < 3; kt++) {
        const int k0 = kt * 16;
        const float* Ap = g_ao + ((size_t)(b0 * Hh + (k0 >> 6)) * Ss + s0) * HD + (k0 & 63);
        g_fill(dyn, kt * STG, Ap, HD, Bb0 + k0, tid);
        CPA_COMMIT();
    }

    for (int it = 0; it < NK; it++) {
        const int rem = (NK - 1) - it;
        if (rem >= 2) CPA_WAIT2(); else if (rem == 1) CPA_WAIT1(); else CPA_WAIT0();
        __syncthreads();
        const int ft = it + 3;
        if (ft < NK) {
            const int k0 = ft * 16;
            const float* Ap = g_ao + ((size_t)(b0 * Hh + (k0 >> 6)) * Ss + s0) * HD + (k0 & 63);
            g_fill(dyn, (ft & 3) * STG, Ap, HD, Bb0 + k0, tid);
            CPA_COMMIT();
        }
        const unsigned stb = smem_base + (it & 3) * STG;
        GEMM_COMPUTE_STAGE(stb);
    }

#pragma unroll
    for (int mf = 0; mf < 2; mf++) {
#pragma unroll
        for (int nf = 0; nf < 8; nf++) {
            const int ncol = wn * 64 + nf * 8 + 2 * tig;
            const float bi0 = bias[bn + ncol], bi1 = bias[bn + ncol + 1];
#pragma unroll
            for (int rr = 0; rr < 2; rr++) {
                const int m = bm + wm * 32 + mf * 16 + gid + rr * 8;
                out[(size_t)m * Dd + bn + ncol]     = acc[mf][nf][rr * 2]     + bi0;
                out[(size_t)m * Dd + bn + ncol + 1] = acc[mf][nf][rr * 2 + 1] + bi1;
            }
        }
    }
}

// ---------------------------------------------------------------------------
// Kernel 2: causal flash attention (unchanged from R10 / best-known).
// ---------------------------------------------------------------------------
#define SM_KS 0
#define SM_VS (32*68*4)
#define SM_PS (SM_VS + 32*72*4)
#define SM_TOT (SM_PS + 128*36*4)

__global__ void __launch_bounds__(128, 2) attn_mma()
{
    __shared__ __align__(16) unsigned char smraw[SM_TOT];
    typedef unsigned (*arr68)[68];
    typedef unsigned (*arr72)[72];
    typedef unsigned (*arr36)[36];
    arr68 Qstage = (arr68)smraw;
    arr68 Ks = (arr68)(smraw + SM_KS);
    arr72 Vs = (arr72)(smraw + SM_VS);
    arr36 Ps = (arr36)(smraw + SM_PS);

    const int bh = blockIdx.y;
    const int qt = gridDim.x - 1 - (int)blockIdx.x;
    const int q0 = qt * 128;
    const int tid = threadIdx.x;
    const int warp = tid >> 5, lane = tid & 31;
    const int gid = lane >> 2, tig = lane & 3;
    const int w32 = warp * 32;

    const float* Qg = g_q + ((size_t)bh * Ss + q0) * HD;
#pragma unroll
    for (int i = 0; i < 16; i++) {
        const int idx = tid + i * 128;
        const int r = idx >> 4, c = (idx & 15) * 4;
        float4 a = *(const float4*)(Qg + r * HD + c);
        uint4 u = { f2tf(a.x * 0.125f), f2tf(a.y * 0.125f),
                    f2tf(a.z * 0.125f), f2tf(a.w * 0.125f) };
        *(uint4*)&Qstage[r][c] = u;
    }
    __syncthreads();

    unsigned qf[8][2][4];
#pragma unroll
    for (int kk = 0; kk < 8; kk++) {
        const int kb = kk * 8;
#pragma unroll
        for (int mf = 0; mf < 2; mf++) {
            const int rb = w32 + mf * 16 + gid;
            qf[kk][mf][0] = Qstage[rb    ][kb + tig];
            qf[kk][mf][1] = Qstage[rb + 8][kb + tig];
            qf[kk][mf][2] = Qstage[rb    ][kb + tig + 4];
            qf[kk][mf][3] = Qstage[rb + 8][kb + tig + 4];
        }
    }
    __syncthreads();

    float o[2][8][4] = {};
    float m[2][2] = { {-1e30f,-1e30f}, {-1e30f,-1e30f} };
    float l[2][2] = { {0.f,0.f}, {0.f,0.f} };

    const int nkt = (q0 + 128) / 32;

    uint4 rk[4], rv[4];
#pragma unroll
    for (int i = 0; i < 4; i++) {
        const int idx = tid + i * 128;
        const int r = idx >> 4, c = (idx & 15) * 4;
        rk[i] = *(const uint4*)(g_k + ((size_t)bh * Ss + r) * HD + c);
        rv[i] = *(const uint4*)(g_v + ((size_t)bh * Ss + r) * HD + c);
    }

    for (int kt = 0; kt < nkt; kt++) {
        const int k0 = kt * 32;
        __syncthreads();
#pragma unroll
        for (int i = 0; i < 4; i++) {
            const int idx = tid + i * 128;
            const int r = idx >> 4, c = (idx & 15) * 4;
            *(uint4*)&Ks[r][c] = rk[i];
            *(uint4*)&Vs[r][c] = rv[i];
        }
        __syncthreads();

        if (kt + 1 < nkt) {
            const int kn0 = k0 + 32;
#pragma unroll
            for (int i = 0; i < 4; i++) {
                const int idx = tid + i * 128;
                const int r = idx >> 4, c = (idx & 15) * 4;
                rk[i] = *(const uint4*)(g_k + ((size_t)bh * Ss + kn0 + r) * HD + c);
                rv[i] = *(const uint4*)(g_v + ((size_t)bh * Ss + kn0 + r) * HD + c);
            }
        }

        if (k0 <= q0 + w32 + 31) {
            float s[2][4][4] = {};
#pragma unroll
            for (int kk = 0; kk < 8; kk++) {
                const int kb = kk * 8;
#pragma unroll
                for (int nf = 0; nf < 4; nf++) {
                    const int cb = nf * 8 + gid;
                    unsigned b0 = Ks[cb][kb + tig];
                    unsigned b1 = Ks[cb][kb + tig + 4];
                    mma_tf32(s[0][nf], qf[kk][0][0], qf[kk][0][1],
                                       qf[kk][0][2], qf[kk][0][3], b0, b1);
                    mma_tf32(s[1][nf], qf[kk][1][0], qf[kk][1][1],
                                       qf[kk][1][2], qf[kk][1][3], b0, b1);
                }
            }

            if (k0 + 32 > q0 + w32) {
#pragma unroll
                for (int mf = 0; mf < 2; mf++) {
                    const int r0 = q0 + w32 + mf * 16 + gid, r1 = r0 + 8;
#pragma unroll
                    for (int nf = 0; nf < 4; nf++) {
                        const int cg = k0 + nf * 8 + 2 * tig;
                        if (cg     > r0) s[mf][nf][0] = -1e30f;
                        if (cg + 1 > r0) s[mf][nf][1] = -1e30f;
                        if (cg     > r1) s[mf][nf][2] = -1e30f;
                        if (cg + 1 > r1) s[mf][nf][3] = -1e30f;
                    }
                }
            }

#pragma unroll
            for (int mf = 0; mf < 2; mf++) {
                float t0 = -1e30f, t1 = -1e30f;
#pragma unroll
                for (int nf = 0; nf < 4; nf++) {
                    t0 = fmaxf(t0, fmaxf(s[mf][nf][0], s[mf][nf][1]));
                    t1 = fmaxf(t1, fmaxf(s[mf][nf][2], s[mf][nf][3]));
                }
                t0 = fmaxf(t0, __shfl_xor_sync(~0u, t0, 1));
                t0 = fmaxf(t0, __shfl_xor_sync(~0u, t0, 2));
                t1 = fmaxf(t1, __shfl_xor_sync(~0u, t1, 1));
                t1 = fmaxf(t1, __shfl_xor_sync(~0u, t1, 2));

                const float nm0 = fmaxf(m[mf][0], t0), nm1 = fmaxf(m[mf][1], t1);
                const float cr0 = __expf(m[mf][0] - nm0), cr1 = __expf(m[mf][1] - nm1);
                l[mf][0] *= cr0; l[mf][1] *= cr1;
#pragma unroll
                for (int nf = 0; nf < 8; nf++) {
                    o[mf][nf][0] *= cr0; o[mf][nf][1] *= cr0;
                    o[mf][nf][2] *= cr1; o[mf][nf][3] *= cr1;
                }
                m[mf][0] = nm0; m[mf][1] = nm1;

                float ls0 = 0.f, ls1 = 0.f;
#pragma unroll
                for (int nf = 0; nf < 4; nf++) {
                    const float p0 = __expf(s[mf][nf][0] - nm0);
                    const float p1 = __expf(s[mf][nf][1] - nm0);
                    const float p2 = __expf(s[mf][nf][2] - nm1);
                    const float p3 = __expf(s[mf][nf][3] - nm1);
                    ls0 += p0 + p1; ls1 += p2 + p3;
                    uint2 w01 = { f2tf(p0), f2tf(p1) };
                    uint2 w23 = { f2tf(p2), f2tf(p3) };
                    const int rb = w32 + mf * 16 + gid;
                    *(uint2*)&Ps[rb    ][nf * 8 + 2 * tig] = w01;
                    *(uint2*)&Ps[rb + 8][nf * 8 + 2 * tig] = w23;
                }
                ls0 += __shfl_xor_sync(~0u, ls0, 1);
                ls0 += __shfl_xor_sync(~0u, ls0, 2);
                ls1 += __shfl_xor_sync(~0u, ls1, 1);
                ls1 += __shfl_xor_sync(~0u, ls1, 2);
                l[mf][0] += ls0; l[mf][1] += ls1;
            }

            __syncwarp();
#pragma unroll
            for (int kk = 0; kk < 4; kk++) {
                const int kb = kk * 8;
                unsigned af[2][4];
#pragma unroll
                for (int mf = 0; mf < 2; mf++) {
                    const int rb = w32 + mf * 16 + gid;
                    af[mf][0] = Ps[rb    ][kb + tig];
                    af[mf][1] = Ps[rb + 8][kb + tig];
                    af[mf][2] = Ps[rb    ][kb + tig + 4];
                    af[mf][3] = Ps[rb + 8][kb + tig + 4];
                }
#pragma unroll
                for (int nf = 0; nf < 8; nf++) {
                    const int cb = nf * 8 + gid;
                    unsigned b0 = Vs[kb + tig    ][cb];
                    unsigned b1 = Vs[kb + tig + 4][cb];
                    mma_tf32(o[0][nf], af[0][0], af[0][1], af[0][2], af[0][3], b0, b1);
                    mma_tf32(o[1][nf], af[1][0], af[1][1], af[1][2], af[1][3], b0, b1);
                }
            }
        }
    }

#pragma unroll
    for (int mf = 0; mf < 2; mf++) {
        const float inv0 = 1.f / l[mf][0], inv1 = 1.f / l[mf][1];
        float* O0 = g_ao + ((size_t)bh * Ss + q0 + w32 + mf * 16 + gid) * HD;
        float* O1 = O0 + 8 * HD;
#pragma unroll
        for (int nf = 0; nf < 8; nf++) {
            const int cg = nf * 8 + 2 * tig;
            O0[cg]     = f2tff(o[mf][nf][0] * inv0);
            O0[cg + 1] = f2tff(o[mf][nf][1] * inv0);
            O1[cg]     = f2tff(o[mf][nf][2] * inv1);
            O1[cg + 1] = f2tff(o[mf][nf][3] * inv1);
        }
    }
}

// ---------------------------------------------------------------------------
extern "C" void kernel_launch(void* const* d_in, const int* in_sizes, int n_in,
                              void* d_out, int out_size)
{
    const float* hs  = (const float*)d_in[0];   // hidden_states [B,S,D]
    const float* caw = (const float*)d_in[1];   // c_attn_w [D,3D]
    const float* cab = (const float*)d_in[2];   // c_attn_b [3D]
    const float* cpw = (const float*)d_in[3];   // c_proj_w [D,D]
    const float* cpb = (const float*)d_in[4];   // c_proj_b [D]
    float* out = (float*)d_out;                 // [B,S,D] fp32

    cudaFuncSetAttribute(qkv_gemm,  cudaFuncAttributeMaxDynamicSharedMemorySize, GEMM_DYN);
    cudaFuncSetAttribute(proj_gemm, cudaFuncAttributeMaxDynamicSharedMemorySize, GEMM_DYN);

    float *xr, *wrt, *wprt;
    cudaGetSymbolAddress((void**)&xr,   g_xr);
    cudaGetSymbolAddress((void**)&wrt,  g_wrt);
    cudaGetSymbolAddress((void**)&wprt, g_wprt);

    round_copy<<<(Mm*Dd/4 + 255)/256, 256>>>(hs, xr, Mm*Dd/4);
    round_transpose<<<dim3(N3/32, Dd/32), 256>>>(caw, wrt, Dd, N3);
    round_transpose<<<dim3(Dd/32, Dd/32), 256>>>(cpw, wprt, Dd, Dd);

    qkv_gemm<<<dim3(N3/128, Mm/128), 256, GEMM_DYN>>>(cab);
    attn_mma<<<dim3(Ss/128, Bb*Hh), 128>>>();
    proj_gemm<<<dim3(Dd/128, Mm/128), 256, GEMM_DYN>>>(cpb, out);
}